// round 8
// baseline (speedup 1.0000x reference)
#include <cuda_runtime.h>
#include <cuda_bf16.h>

#define HIDDEN 2048
#define INTER  1408
#define TOP_K  4

// Scratch for weighted intermediate activations: topk_w[e] * silu(gate)*up
__device__ float g_inter[TOP_K * INTER];

// ---------------------------------------------------------------------------
// Kernel 1: gate/up GEMV + SiLU with embedded PARTIAL (75%) L2 prefetch of
// the down matrices. Block (bx, e) owns the 64 KB slice [bx*64K,(bx+1)*64K)
// of down[topk_idx[e]] and prefetches its first 48 KB. The 25% holes are
// spread uniformly at 16 KB granularity, so kernel-2 blocks all carry the
// same L2-hit / DRAM-miss mix, and the down misses stream from DRAM while
// the hits stream from L2 (two different resources) during kernel 2.
// grid: (176, 4), block: 256 threads (8 warps, 1 row per warp)
// ---------------------------------------------------------------------------
__global__ __launch_bounds__(256)
void moe_gate_up_kernel(const float* __restrict__ x,
                        const int*   __restrict__ topk_idx,
                        const float* __restrict__ topk_w,
                        const float* __restrict__ gate_all,
                        const float* __restrict__ up_all,
                        const float* __restrict__ down_all)
{
    __shared__ float4 x_s[HIDDEN / 4];   // 8 KB

    const int tid  = threadIdx.x;
    const int lane = tid & 31;
    const int warp = tid >> 5;
    const int e    = blockIdx.y;                // expert slot 0..3
    const long long ex = topk_idx[e];

    // --- Partial prefetch: first 48 KB of this block's 64 KB slice.
    {
        const char* dbase = reinterpret_cast<const char*>(
            down_all + ex * (long long)(HIDDEN * INTER));
        const long long off = (long long)blockIdx.x * 65536 + tid * 128;
        asm volatile("prefetch.global.L2 [%0];" :: "l"(dbase + off));        // [0,32K)
        if (tid < 128)
            asm volatile("prefetch.global.L2 [%0];" :: "l"(dbase + off + 32768)); // [32K,48K)
    }

    // Stage x into shared memory: 512 float4 / 256 threads = 2 each
    const float4* x4 = reinterpret_cast<const float4*>(x);
    x_s[tid]       = x4[tid];
    x_s[tid + 256] = x4[tid + 256];
    __syncthreads();

    const int row = blockIdx.x * 8 + warp;      // 0..1407

    const float4* g4 = reinterpret_cast<const float4*>(
        gate_all + (ex * INTER + row) * (long long)HIDDEN);
    const float4* u4 = reinterpret_cast<const float4*>(
        up_all   + (ex * INTER + row) * (long long)HIDDEN);

    float gacc = 0.f, uacc = 0.f;
    // 512 float4 per row, 32 lanes -> 16 iterations
#pragma unroll
    for (int j = 0; j < 16; j++) {
        const int idx = j * 32 + lane;
        const float4 xv = x_s[idx];
        const float4 gv = __ldcs(g4 + idx);   // streaming: evict-first
        const float4 uv = __ldcs(u4 + idx);
        gacc += gv.x * xv.x + gv.y * xv.y + gv.z * xv.z + gv.w * xv.w;
        uacc += uv.x * xv.x + uv.y * xv.y + uv.z * xv.z + uv.w * xv.w;
    }

    // warp reduce
#pragma unroll
    for (int off = 16; off > 0; off >>= 1) {
        gacc += __shfl_xor_sync(0xFFFFFFFFu, gacc, off);
        uacc += __shfl_xor_sync(0xFFFFFFFFu, uacc, off);
    }

    if (lane == 0) {
        const float w = topk_w[e];
        const float silu = gacc / (1.0f + __expf(-gacc));
        g_inter[e * INTER + row] = w * silu * uacc;
    }
}

// ---------------------------------------------------------------------------
// Kernel 2: out[h] = sum_e dot(down[ex_e][h][:], g_inter[e][:])
// One warp per h across ALL 4 experts: 44 fully-unrolled independent LDG.128
// per warp. ~75% of the reads hit L2 (prefetched), ~25% stream from the
// otherwise-idle DRAM. g_inter (22.5 KB) staged in smem per block. Single
// write per h, fixed expert order -> deterministic, no memset, no atomics.
// grid: 256, block: 256 threads (8 warps, 1 h per warp)
// ---------------------------------------------------------------------------
__global__ __launch_bounds__(256)
void moe_down_kernel(const int*   __restrict__ topk_idx,
                     const float* __restrict__ down_all,
                     float*       __restrict__ out)
{
    __shared__ float4 gi_s[TOP_K * INTER / 4];   // 1408 float4 = 22.5 KB

    const int tid  = threadIdx.x;
    const int lane = tid & 31;
    const int warp = tid >> 5;

    // Stage g_inter: 1408 float4 / 256 threads
    const float4* gi4 = reinterpret_cast<const float4*>(g_inter);
    for (int k = tid; k < TOP_K * INTER / 4; k += 256)
        gi_s[k] = gi4[k];
    __syncthreads();

    const int h = blockIdx.x * 8 + warp;     // 0..2047

    const long long e0 = topk_idx[0];
    const long long e1 = topk_idx[1];
    const long long e2 = topk_idx[2];
    const long long e3 = topk_idx[3];
    const float4* d0 = reinterpret_cast<const float4*>(down_all + (e0 * HIDDEN + h) * (long long)INTER);
    const float4* d1 = reinterpret_cast<const float4*>(down_all + (e1 * HIDDEN + h) * (long long)INTER);
    const float4* d2 = reinterpret_cast<const float4*>(down_all + (e2 * HIDDEN + h) * (long long)INTER);
    const float4* d3 = reinterpret_cast<const float4*>(down_all + (e3 * HIDDEN + h) * (long long)INTER);

    float acc0 = 0.f, acc1 = 0.f, acc2 = 0.f, acc3 = 0.f;
    // 352 float4 per expert row, 32 lanes -> 11 iterations x 4 experts
#pragma unroll
    for (int j = 0; j < 11; j++) {
        const int idx = j * 32 + lane;
        const float4 a0 = __ldg(d0 + idx);
        const float4 a1 = __ldg(d1 + idx);
        const float4 a2 = __ldg(d2 + idx);
        const float4 a3 = __ldg(d3 + idx);
        const float4 v0 = gi_s[idx];
        const float4 v1 = gi_s[idx + 352];
        const float4 v2 = gi_s[idx + 704];
        const float4 v3 = gi_s[idx + 1056];
        acc0 += a0.x * v0.x + a0.y * v0.y + a0.z * v0.z + a0.w * v0.w;
        acc1 += a1.x * v1.x + a1.y * v1.y + a1.z * v1.z + a1.w * v1.w;
        acc2 += a2.x * v2.x + a2.y * v2.y + a2.z * v2.z + a2.w * v2.w;
        acc3 += a3.x * v3.x + a3.y * v3.y + a3.z * v3.z + a3.w * v3.w;
    }

    float acc = (acc0 + acc1) + (acc2 + acc3);
#pragma unroll
    for (int off = 16; off > 0; off >>= 1)
        acc += __shfl_xor_sync(0xFFFFFFFFu, acc, off);

    if (lane == 0)
        out[h] = acc;
}

extern "C" void kernel_launch(void* const* d_in, const int* in_sizes, int n_in,
                              void* d_out, int out_size)
{
    const float* x        = (const float*)d_in[0];   // (1, 2048, 1, 1)
    const int*   topk_idx = (const int*)  d_in[1];   // (4,)
    const float* topk_w   = (const float*)d_in[2];   // (4,)
    const float* gate_all = (const float*)d_in[3];   // (60, 1408, 2048)
    const float* up_all   = (const float*)d_in[4];   // (60, 1408, 2048)
    const float* down_all = (const float*)d_in[5];   // (60, 2048, 1408)
    float* out = (float*)d_out;                      // (1, 2048, 1, 1)

    dim3 grid1(INTER / 8, TOP_K);
    moe_gate_up_kernel<<<grid1, 256>>>(x, topk_idx, topk_w,
                                       gate_all, up_all, down_all);

    moe_down_kernel<<<HIDDEN / 8, 256>>>(topk_idx, down_all, out);
}

// round 9
// speedup vs baseline: 1.0817x; 1.0817x over previous
#include <cuda_runtime.h>
#include <cuda_bf16.h>

#define HIDDEN 2048
#define INTER  1408
#define TOP_K  4

// Scratch for weighted intermediate activations: topk_w[e] * silu(gate)*up
__device__ float g_inter[TOP_K * INTER];

// ---------------------------------------------------------------------------
// Kernel 1 (identical to the 25.06us best): gate/up GEMV + SiLU with
// embedded FULL L2 prefetch of the down matrices. Block (bx, e) prefetches
// bytes [bx*64K, (bx+1)*64K) of down[topk_idx[e]] (176 x 64 KB = 11.53 MB
// per expert, exact), so the 46 MB down fetch streams concurrently with the
// 92 MB gate/up stream in one DRAM window.
// grid: (176, 4), block: 256 threads (8 warps, 1 row per warp)
// ---------------------------------------------------------------------------
__global__ __launch_bounds__(256)
void moe_gate_up_kernel(const float* __restrict__ x,
                        const int*   __restrict__ topk_idx,
                        const float* __restrict__ topk_w,
                        const float* __restrict__ gate_all,
                        const float* __restrict__ up_all,
                        const float* __restrict__ down_all)
{
    __shared__ float4 x_s[HIDDEN / 4];   // 8 KB

    const int tid  = threadIdx.x;
    const int lane = tid & 31;
    const int warp = tid >> 5;
    const int e    = blockIdx.y;                // expert slot 0..3
    const long long ex = topk_idx[e];

    // --- Embedded full prefetch of this expert's down block slice
    {
        const char* dbase = reinterpret_cast<const char*>(
            down_all + ex * (long long)(HIDDEN * INTER));
        const long long off = (long long)blockIdx.x * 65536 + tid * 128;
        asm volatile("prefetch.global.L2 [%0];" :: "l"(dbase + off));
        asm volatile("prefetch.global.L2 [%0];" :: "l"(dbase + off + 32768));
    }

    // Stage x into shared memory: 512 float4 / 256 threads = 2 each
    const float4* x4 = reinterpret_cast<const float4*>(x);
    x_s[tid]       = x4[tid];
    x_s[tid + 256] = x4[tid + 256];
    __syncthreads();

    const int row = blockIdx.x * 8 + warp;      // 0..1407

    const float4* g4 = reinterpret_cast<const float4*>(
        gate_all + (ex * INTER + row) * (long long)HIDDEN);
    const float4* u4 = reinterpret_cast<const float4*>(
        up_all   + (ex * INTER + row) * (long long)HIDDEN);

    float gacc = 0.f, uacc = 0.f;
    // 512 float4 per row, 32 lanes -> 16 iterations
#pragma unroll
    for (int j = 0; j < 16; j++) {
        const int idx = j * 32 + lane;
        const float4 xv = x_s[idx];
        const float4 gv = __ldcs(g4 + idx);   // streaming: evict-first
        const float4 uv = __ldcs(u4 + idx);
        gacc += gv.x * xv.x + gv.y * xv.y + gv.z * xv.z + gv.w * xv.w;
        uacc += uv.x * xv.x + uv.y * xv.y + uv.z * xv.z + uv.w * xv.w;
    }

    // warp reduce
#pragma unroll
    for (int off = 16; off > 0; off >>= 1) {
        gacc += __shfl_xor_sync(0xFFFFFFFFu, gacc, off);
        uacc += __shfl_xor_sync(0xFFFFFFFFu, uacc, off);
    }

    if (lane == 0) {
        const float w = topk_w[e];
        const float silu = gacc / (1.0f + __expf(-gacc));
        g_inter[e * INTER + row] = w * silu * uacc;
    }
}

// ---------------------------------------------------------------------------
// Kernel 2: out[h] = sum_e dot(down[ex_e][h][:], g_inter[e][:])
// TWO warps per h (expert pairs {0,1} and {2,3}), 4 h per block ->
// grid 512 x 256 thr = 4096 warp-tasks (2x the previous concurrency,
// ~40% occupancy) to saturate LTS. Halves combined in smem with a fixed-
// order add: deterministic, no atomics, no memset.
// grid: 512, block: 256 threads (8 warps: warp = 2*h_local + pair)
// ---------------------------------------------------------------------------
__global__ __launch_bounds__(256)
void moe_down_kernel(const int*   __restrict__ topk_idx,
                     const float* __restrict__ down_all,
                     float*       __restrict__ out)
{
    __shared__ float4 gi_s[TOP_K * INTER / 4];   // 1408 float4 = 22.5 KB
    __shared__ float  partial[8];

    const int tid  = threadIdx.x;
    const int lane = tid & 31;
    const int warp = tid >> 5;
    const int hloc = warp >> 1;              // 0..3
    const int p    = warp & 1;               // expert pair 0..1

    // Stage g_inter: 1408 float4 / 256 threads = 5.5 -> loop
    const float4* gi4 = reinterpret_cast<const float4*>(g_inter);
    for (int k = tid; k < TOP_K * INTER / 4; k += 256)
        gi_s[k] = gi4[k];
    __syncthreads();

    const int h = blockIdx.x * 4 + hloc;     // 0..2047

    const long long e0 = topk_idx[2 * p];
    const long long e1 = topk_idx[2 * p + 1];
    const float4* d0 = reinterpret_cast<const float4*>(
        down_all + (e0 * HIDDEN + h) * (long long)INTER);
    const float4* d1 = reinterpret_cast<const float4*>(
        down_all + (e1 * HIDDEN + h) * (long long)INTER);
    const float4* v0p = gi_s + 2 * p * 352;
    const float4* v1p = gi_s + (2 * p + 1) * 352;

    float acc0 = 0.f, acc1 = 0.f;
    // 352 float4 per expert row, 32 lanes -> 11 iterations x 2 experts
#pragma unroll
    for (int j = 0; j < 11; j++) {
        const int idx = j * 32 + lane;
        const float4 a0 = __ldg(d0 + idx);
        const float4 a1 = __ldg(d1 + idx);
        const float4 v0 = v0p[idx];
        const float4 v1 = v1p[idx];
        acc0 += a0.x * v0.x + a0.y * v0.y + a0.z * v0.z + a0.w * v0.w;
        acc1 += a1.x * v1.x + a1.y * v1.y + a1.z * v1.z + a1.w * v1.w;
    }

    float acc = acc0 + acc1;
#pragma unroll
    for (int off = 16; off > 0; off >>= 1)
        acc += __shfl_xor_sync(0xFFFFFFFFu, acc, off);

    if (lane == 0) partial[warp] = acc;
    __syncthreads();

    if (tid < 4)
        out[blockIdx.x * 4 + tid] = partial[2 * tid] + partial[2 * tid + 1];
}

extern "C" void kernel_launch(void* const* d_in, const int* in_sizes, int n_in,
                              void* d_out, int out_size)
{
    const float* x        = (const float*)d_in[0];   // (1, 2048, 1, 1)
    const int*   topk_idx = (const int*)  d_in[1];   // (4,)
    const float* topk_w   = (const float*)d_in[2];   // (4,)
    const float* gate_all = (const float*)d_in[3];   // (60, 1408, 2048)
    const float* up_all   = (const float*)d_in[4];   // (60, 1408, 2048)
    const float* down_all = (const float*)d_in[5];   // (60, 2048, 1408)
    float* out = (float*)d_out;                      // (1, 2048, 1, 1)

    dim3 grid1(INTER / 8, TOP_K);
    moe_gate_up_kernel<<<grid1, 256>>>(x, topk_idx, topk_w,
                                       gate_all, up_all, down_all);

    moe_down_kernel<<<HIDDEN / 4, 256>>>(topk_idx, down_all, out);
}